// round 9
// baseline (speedup 1.0000x reference)
#include <cuda_runtime.h>
#include <cstdint>
#include <math.h>

// Problem constants (fixed by the dataset)
#define NMAX 50000
#define EMAX 600000
#define FIN  64
#define HID  128

// ---------------------------------------------------------------------------
// Scratch (device globals; no allocation allowed in kernel_launch)
// ---------------------------------------------------------------------------
__device__ float g_dis[NMAX];              // deg, then d^{-1/2}
__device__ int   g_cnt[NMAX];              // in-degree histogram (by dst)
__device__ int   g_cur[NMAX];              // scatter cursors
__device__ int   g_row[NMAX + 1];          // CSR row offsets (by dst)
__device__ int   g_blksum[256];            // scan block partials
__device__ int2  g_meta[EMAX];             // per-edge {src, w_bits} (CSR order)
__device__ float g_S1[NMAX * FIN];         // P x
__device__ float g_S2[NMAX * FIN];         // P^2 x
__device__ float g_S3[NMAX * FIN];         // P^3 x
// B operand: [n' 0..255][k' 0..255], n' interleaved (even=z feat, odd=h feat),
// k' permuted within 8-groups so (k, k+4) are adjacent; values tf32-rounded.
__device__ float g_WcatT[256 * 256];
__device__ float g_bias[256];              // interleaved: [2j]=bz_j, [2j+1]=bh_j

// ---------------------------------------------------------------------------
// Setup kernels
// ---------------------------------------------------------------------------
__global__ void k_zero_small(int n) {      // dis + cnt + cur
    int i = blockIdx.x * blockDim.x + threadIdx.x;
    if (i < n) { g_dis[i] = 0.0f; g_cnt[i] = 0; g_cur[i] = 0; }
}

// deg[src] += ew (self-loops removed) ; cnt[dst] += 1
__global__ void k_deg_hist(const int* __restrict__ ei, const float* __restrict__ ew, int e) {
    int i = blockIdx.x * blockDim.x + threadIdx.x;
    if (i >= e) return;
    int s = ei[i], d = ei[e + i];
    if (s != d) atomicAdd(&g_dis[s], ew[i]);
    atomicAdd(&g_cnt[d], 1);
}

// ---------------------------------------------------------------------------
// Multi-block exclusive scan of g_cnt -> g_row  (3 phases, full-chip parallel)
// Phase 1 also finalizes g_dis (deg -> d^{-1/2}) — same domain & dependency.
// All __shfl_*_sync calls are executed by FULL warps (mask 0xffffffff).
// ---------------------------------------------------------------------------
#define SCAN_BLK 512

__global__ __launch_bounds__(SCAN_BLK) void k_scan1(int n) {
    __shared__ int ws[32];
    int t = threadIdx.x;
    int i = blockIdx.x * SCAN_BLK + t;
    int v = 0;
    if (i < n) {
        v = g_cnt[i];
        float dg = g_dis[i];                         // fused k_dis
        g_dis[i] = (dg > 0.f) ? rsqrtf(dg) : 0.f;
    }
    int lane = t & 31, w = t >> 5;
    if (t < 32) ws[t] = 0;
    __syncthreads();
    int s = v;
#pragma unroll
    for (int o = 1; o < 32; o <<= 1) {
        int u = __shfl_up_sync(0xffffffffu, s, o);
        if (lane >= o) s += u;
    }
    if (lane == 31) ws[w] = s;
    __syncthreads();
    if (w == 0) {                                    // ALL 32 lanes of warp 0
        int u = ws[lane];
#pragma unroll
        for (int o = 1; o < 32; o <<= 1) {
            int z = __shfl_up_sync(0xffffffffu, u, o);
            if (lane >= o) u += z;
        }
        ws[lane] = u;
    }
    __syncthreads();
    int excl = (s - v) + (w ? ws[w - 1] : 0);
    if (i < n) g_row[i] = excl;
    if (t == SCAN_BLK - 1) g_blksum[blockIdx.x] = excl + v;
}

__global__ __launch_bounds__(128) void k_scan2(int n, int nblk) {
    __shared__ int ws[32];
    int t = threadIdx.x;
    int v = (t < nblk) ? g_blksum[t] : 0;
    int lane = t & 31, w = t >> 5;
    if (t < 32) ws[t] = 0;
    __syncthreads();
    int s = v;
#pragma unroll
    for (int o = 1; o < 32; o <<= 1) {
        int u = __shfl_up_sync(0xffffffffu, s, o);
        if (lane >= o) s += u;
    }
    if (lane == 31) ws[w] = s;
    __syncthreads();
    if (w == 0) {
        int u = ws[lane];
#pragma unroll
        for (int o = 1; o < 32; o <<= 1) {
            int z = __shfl_up_sync(0xffffffffu, u, o);
            if (lane >= o) u += z;
        }
        ws[lane] = u;
    }
    __syncthreads();
    int excl = (s - v) + (w ? ws[w - 1] : 0);
    if (t < nblk) g_blksum[t] = excl;
    if (t == nblk - 1) g_row[n] = excl + v;
}

__global__ __launch_bounds__(SCAN_BLK) void k_scan3(int n) {
    int i = blockIdx.x * SCAN_BLK + threadIdx.x;
    if (i < n) g_row[i] += g_blksum[blockIdx.x];
}

// w = -dis[src]*ew*dis[dst] (0 on self loops); scatter {src, w} into CSR slots
__global__ void k_edgew_scatter(const int* __restrict__ ei, const float* __restrict__ ew, int e) {
    int i = blockIdx.x * blockDim.x + threadIdx.x;
    if (i >= e) return;
    int s = ei[i], d = ei[e + i];
    float w = (s == d) ? 0.f : -g_dis[s] * ew[i] * g_dis[d];
    int pos = g_row[d] + atomicAdd(&g_cur[d], 1);
    g_meta[pos] = make_int2(s, __float_as_int(w));
}

// ---------------------------------------------------------------------------
// Gather SpMM: out[node] = sum_e w_e * in[src_e]  (one warp per node; no atomics)
// Edge loop unrolled x4: 4 metas then 4 independent row gathers in flight.
// which: 1 -> x->S1 ; 2 -> S1->S2 ; 3 -> S2->S3
// ---------------------------------------------------------------------------
__global__ __launch_bounds__(256) void k_prop_csr(const float* __restrict__ x,
                                                  int which, int n) {
    int node = (blockIdx.x * blockDim.x + threadIdx.x) >> 5;
    if (node >= n) return;
    int lane = threadIdx.x & 31;
    const float* in = (which == 1) ? x : (which == 2) ? g_S1 : g_S2;
    float* out = (which == 1) ? g_S1 : (which == 2) ? g_S2 : g_S3;
    int beg = g_row[node], end = g_row[node + 1];
    float ax = 0.f, ay = 0.f;
    int e = beg;
    for (; e + 4 <= end; e += 4) {
        int2 m0 = __ldg(g_meta + e);
        int2 m1 = __ldg(g_meta + e + 1);
        int2 m2 = __ldg(g_meta + e + 2);
        int2 m3 = __ldg(g_meta + e + 3);
        float2 v0 = __ldg(reinterpret_cast<const float2*>(in + m0.x * 64) + lane);
        float2 v1 = __ldg(reinterpret_cast<const float2*>(in + m1.x * 64) + lane);
        float2 v2 = __ldg(reinterpret_cast<const float2*>(in + m2.x * 64) + lane);
        float2 v3 = __ldg(reinterpret_cast<const float2*>(in + m3.x * 64) + lane);
        float w0 = __int_as_float(m0.y), w1 = __int_as_float(m1.y);
        float w2 = __int_as_float(m2.y), w3 = __int_as_float(m3.y);
        ax += w0 * v0.x + w1 * v1.x + w2 * v2.x + w3 * v3.x;
        ay += w0 * v0.y + w1 * v1.y + w2 * v2.y + w3 * v3.y;
    }
    for (; e < end; e++) {
        int2 m = __ldg(g_meta + e);
        float2 v = __ldg(reinterpret_cast<const float2*>(in + m.x * 64) + lane);
        float w = __int_as_float(m.y);
        ax += w * v.x;
        ay += w * v.y;
    }
    reinterpret_cast<float2*>(out + node * 64)[lane] = make_float2(ax, ay);
}

// ---------------------------------------------------------------------------
// tf32 round helper — destination of cvt.*.tf32 must be a b32 register.
// ---------------------------------------------------------------------------
__device__ __forceinline__ float tf32_rna(float v) {
    uint32_t r;
    asm("cvt.rna.tf32.f32 %0, %1;" : "=r"(r) : "f"(v));
    return __uint_as_float(r);
}

// ---------------------------------------------------------------------------
// Build W^T [n'][k'] with column interleave + k permutation + tf32 rounding.
// ---------------------------------------------------------------------------
__global__ void k_wcat(const float* __restrict__ Wxz, const float* __restrict__ Wxh,
                       const float* __restrict__ bxz, const float* __restrict__ bhz,
                       const float* __restrict__ bxh, const float* __restrict__ bhh) {
    int idx = blockIdx.x * blockDim.x + threadIdx.x;
    if (idx < 256 * 256) {
        int np = idx >> 8;
        int kp = idx & 255;
        int j = np >> 1;
        int g = kp >> 3, p = kp & 7;
        int kk = (p >> 1) + (p & 1) * 4;
        int k = g * 8 + kk;
        int kb = k >> 6, f = k & 63;
        float v = (np & 1) ? Wxh[kb * 64 * 128 + f * 128 + j]
                           : Wxz[kb * 64 * 128 + f * 128 + j];
        g_WcatT[np * 256 + kp] = tf32_rna(v);
    }
    if (idx < 256) {
        int j = idx >> 1;
        g_bias[idx] = (idx & 1) ? (bxh[j] + bhh[j]) : (bxz[j] + bhz[j]);
    }
}

// ---------------------------------------------------------------------------
// Legacy-mma tf32 GEMM + fused GRU epilogue + linear head.
// A columns built on the fly from power series:
//   kb0: x ; kb1: S1 ; kb2: 2*S2 - x ; kb3: 4*S3 - 3*S1
// ---------------------------------------------------------------------------
#define A_STRIDE 40
#define B_STRIDE 40
#define SM_A_FLOATS (128 * A_STRIDE)
#define SM_B_FLOATS (256 * B_STRIDE)
#define SM_RED_FLOATS (128 * 4)
#define GEMM_SMEM ((SM_A_FLOATS + SM_B_FLOATS + SM_RED_FLOATS) * 4)

__device__ __forceinline__ void mma_tf32(float* d, uint32_t a0, uint32_t a1,
                                         uint32_t a2, uint32_t a3,
                                         uint32_t b0, uint32_t b1) {
    asm volatile(
        "mma.sync.aligned.m16n8k8.row.col.f32.tf32.tf32.f32 "
        "{%0,%1,%2,%3}, {%4,%5,%6,%7}, {%8,%9}, {%0,%1,%2,%3};"
        : "+f"(d[0]), "+f"(d[1]), "+f"(d[2]), "+f"(d[3])
        : "r"(a0), "r"(a1), "r"(a2), "r"(a3), "r"(b0), "r"(b1));
}

__global__ __launch_bounds__(512, 1) void k_gemm_mma(const float* __restrict__ x,
                                                     const float* __restrict__ linW,
                                                     const float* __restrict__ linb,
                                                     float* __restrict__ out, int n) {
    extern __shared__ __align__(16) float smem[];
    float* As  = smem;                       // [128][A_STRIDE]
    float* Bs  = As + SM_A_FLOATS;           // [256][B_STRIDE]
    float* red = Bs + SM_B_FLOATS;           // [128][4]

    int tid  = threadIdx.x;
    int warp = tid >> 5;
    int lane = tid & 31;
    int wm = warp & 3;
    int wn = warp >> 2;
    int gid = lane >> 2;
    int q   = lane & 3;
    int rbase = blockIdx.x * 128;

    float acc[2][8][4];
#pragma unroll
    for (int mt = 0; mt < 2; mt++)
#pragma unroll
        for (int nt = 0; nt < 8; nt++)
#pragma unroll
            for (int c = 0; c < 4; c++) acc[mt][nt][c] = 0.f;

    int a_row  = tid >> 2;          // 0..127
    int a_quad = tid & 3;           // k-group within chunk (8 k each)
    int b_row  = tid >> 1;          // 0..255
    int b_half = tid & 1;           // 16 k' each

    for (int c = 0; c < 8; c++) {
        __syncthreads();  // previous chunk fully consumed
        // ---- stage A chunk: rows 0..127, k = c*32 .. +32, permuted + tf32 ----
        {
            int kb = c >> 1;
            int f0 = (c & 1) * 32 + a_quad * 8;
            float* dst = As + a_row * A_STRIDE + a_quad * 8;
            int grow = rbase + a_row;
            if (grow < n) {
                long off = (long)grow * 64 + f0;
                float4 v1, v2;
                if (kb == 0) {
                    v1 = __ldg(reinterpret_cast<const float4*>(x + off));
                    v2 = __ldg(reinterpret_cast<const float4*>(x + off + 4));
                } else if (kb == 1) {
                    v1 = __ldg(reinterpret_cast<const float4*>(g_S1 + off));
                    v2 = __ldg(reinterpret_cast<const float4*>(g_S1 + off + 4));
                } else if (kb == 2) {
                    float4 a1 = __ldg(reinterpret_cast<const float4*>(g_S2 + off));
                    float4 a2 = __ldg(reinterpret_cast<const float4*>(g_S2 + off + 4));
                    float4 b1 = __ldg(reinterpret_cast<const float4*>(x + off));
                    float4 b2 = __ldg(reinterpret_cast<const float4*>(x + off + 4));
                    v1 = make_float4(2.f * a1.x - b1.x, 2.f * a1.y - b1.y,
                                     2.f * a1.z - b1.z, 2.f * a1.w - b1.w);
                    v2 = make_float4(2.f * a2.x - b2.x, 2.f * a2.y - b2.y,
                                     2.f * a2.z - b2.z, 2.f * a2.w - b2.w);
                } else {
                    float4 a1 = __ldg(reinterpret_cast<const float4*>(g_S3 + off));
                    float4 a2 = __ldg(reinterpret_cast<const float4*>(g_S3 + off + 4));
                    float4 b1 = __ldg(reinterpret_cast<const float4*>(g_S1 + off));
                    float4 b2 = __ldg(reinterpret_cast<const float4*>(g_S1 + off + 4));
                    v1 = make_float4(4.f * a1.x - 3.f * b1.x, 4.f * a1.y - 3.f * b1.y,
                                     4.f * a1.z - 3.f * b1.z, 4.f * a1.w - 3.f * b1.w);
                    v2 = make_float4(4.f * a2.x - 3.f * b2.x, 4.f * a2.y - 3.f * b2.y,
                                     4.f * a2.z - 3.f * b2.z, 4.f * a2.w - 3.f * b2.w);
                }
                dst[0] = tf32_rna(v1.x); dst[2] = tf32_rna(v1.y);
                dst[4] = tf32_rna(v1.z); dst[6] = tf32_rna(v1.w);
                dst[1] = tf32_rna(v2.x); dst[3] = tf32_rna(v2.y);
                dst[5] = tf32_rna(v2.z); dst[7] = tf32_rna(v2.w);
            } else {
#pragma unroll
                for (int i = 0; i < 8; i++) dst[i] = 0.f;
            }
        }
        // ---- stage B chunk ----
        {
            const float4* src = reinterpret_cast<const float4*>(
                g_WcatT + b_row * 256 + c * 32 + b_half * 16);
            float* dst = Bs + b_row * B_STRIDE + b_half * 16;
#pragma unroll
            for (int j = 0; j < 4; j++) {
                float4 v = __ldg(src + j);
                *reinterpret_cast<float4*>(dst + j * 4) = v;
            }
        }
        __syncthreads();

        // ---- mma over 4 k-groups of 8 ----
#pragma unroll
        for (int g = 0; g < 4; g++) {
            uint32_t af[2][4];
#pragma unroll
            for (int mt = 0; mt < 2; mt++) {
                int r0 = wm * 32 + mt * 16 + gid;
                float2 lo = *reinterpret_cast<const float2*>(As + r0 * A_STRIDE + g * 8 + q * 2);
                float2 hi = *reinterpret_cast<const float2*>(As + (r0 + 8) * A_STRIDE + g * 8 + q * 2);
                af[mt][0] = __float_as_uint(lo.x);
                af[mt][2] = __float_as_uint(lo.y);
                af[mt][1] = __float_as_uint(hi.x);
                af[mt][3] = __float_as_uint(hi.y);
            }
#pragma unroll
            for (int nt = 0; nt < 8; nt++) {
                int nn = wn * 64 + nt * 8 + gid;
                float2 b = *reinterpret_cast<const float2*>(Bs + nn * B_STRIDE + g * 8 + q * 2);
                uint32_t b0 = __float_as_uint(b.x);
                uint32_t b1 = __float_as_uint(b.y);
#pragma unroll
                for (int mt = 0; mt < 2; mt++)
                    mma_tf32(acc[mt][nt], af[mt][0], af[mt][1], af[mt][2], af[mt][3], b0, b1);
            }
        }
    }

    // ---- fused epilogue ----
    float bz[8], bh[8], lw[8];
#pragma unroll
    for (int nt = 0; nt < 8; nt++) {
        int j = wn * 32 + nt * 4 + q;
        bz[nt] = __ldg(g_bias + 2 * j);
        bh[nt] = __ldg(g_bias + 2 * j + 1);
        lw[nt] = __ldg(linW + j);
    }
#pragma unroll
    for (int mt = 0; mt < 2; mt++) {
#pragma unroll
        for (int half = 0; half < 2; half++) {
            float p = 0.f;
#pragma unroll
            for (int nt = 0; nt < 8; nt++) {
                float z = acc[mt][nt][half * 2 + 0] + bz[nt];
                float h = acc[mt][nt][half * 2 + 1] + bh[nt];
                float th;
                asm("tanh.approx.f32 %0, %1;" : "=f"(th) : "f"(h));
                float sg = 1.0f / (1.0f + __expf(z));  // sigmoid(-z)
                p += fmaxf(sg * th, 0.f) * lw[nt];
            }
            p += __shfl_xor_sync(0xffffffffu, p, 1);
            p += __shfl_xor_sync(0xffffffffu, p, 2);
            if (q == 0) {
                int row = wm * 32 + mt * 16 + half * 8 + gid;
                red[row * 4 + wn] = p;
            }
        }
    }
    __syncthreads();
    if (tid < 128) {
        int row = rbase + tid;
        if (row < n) {
            float s = red[tid * 4] + red[tid * 4 + 1] + red[tid * 4 + 2] + red[tid * 4 + 3];
            out[row] = s + __ldg(linb);
        }
    }
}

// ---------------------------------------------------------------------------
// kernel_launch
// ---------------------------------------------------------------------------
extern "C" void kernel_launch(void* const* d_in, const int* in_sizes, int n_in,
                              void* d_out, int out_size) {
    (void)n_in; (void)out_size;
    const float* x    = (const float*)d_in[0];
    const int*   ei   = (const int*)d_in[1];
    const float* ew   = (const float*)d_in[2];
    const float* Wxz  = (const float*)d_in[3];
    const float* bxz  = (const float*)d_in[4];
    const float* bhz  = (const float*)d_in[6];
    const float* Wxh  = (const float*)d_in[11];
    const float* bxh  = (const float*)d_in[12];
    const float* bhh  = (const float*)d_in[14];
    const float* linW = (const float*)d_in[15];
    const float* linb = (const float*)d_in[16];
    float* out = (float*)d_out;

    int n = in_sizes[0] / FIN;   // 50000
    int e = in_sizes[2];         // 600000

    int nblk = (n + SCAN_BLK - 1) / SCAN_BLK;   // 98 for n=50000 (<=128 required)

    // 1) zero small buffers (dis/cnt/cur)
    k_zero_small<<<(n + 255) / 256, 256>>>(n);
    // 2) degree (by src, weighted) + histogram (by dst)
    k_deg_hist<<<(e + 255) / 256, 256>>>(ei, ew, e);
    // 3) CSR row offsets (scan1 also finalizes d^{-1/2})
    k_scan1<<<nblk, SCAN_BLK>>>(n);
    k_scan2<<<1, 128>>>(n, nblk);
    k_scan3<<<nblk, SCAN_BLK>>>(n);
    // 4) normalized weights + CSR meta scatter
    k_edgew_scatter<<<(e + 255) / 256, 256>>>(ei, ew, e);
    // 5) power-series props (gather, no atomics): S1 = Px, S2 = P S1, S3 = P S2
    int pgrid = (n * 32 + 255) / 256;
    k_prop_csr<<<pgrid, 256>>>(x, 1, n);
    k_prop_csr<<<pgrid, 256>>>(x, 2, n);
    k_prop_csr<<<pgrid, 256>>>(x, 3, n);
    // 6) weight concat
    k_wcat<<<256, 256>>>(Wxz, Wxh, bxz, bhz, bxh, bhh);
    // 7) tf32 mma GEMM + GRU epilogue + linear head
    cudaFuncSetAttribute(k_gemm_mma, cudaFuncAttributeMaxDynamicSharedMemorySize,
                         GEMM_SMEM);
    k_gemm_mma<<<(n + 127) / 128, 512, GEMM_SMEM>>>(x, linW, linb, out, n);
}